// round 2
// baseline (speedup 1.0000x reference)
#include <cuda_runtime.h>
#include <cuda_bf16.h>
#include <math.h>
#include <stdint.h>

// Problem constants (fixed by the dataset)
#define D_DIM   1024
#define F_DIM   2048
#define E_NUM   8
#define N_TOK   2048
#define NPAIR   4096   // N_TOK * K (K=2)
#define PADROWS 5120   // NPAIR + E_NUM*BM worst-case padding
#define BM      128
#define BN      64
#define BK      32
#define MAXTILES (PADROWS / BM)   // 40
#define LDA     36     // BK + 4 pad (fp32 elems); 144B row stride, 16B aligned
#define LDB     36

// Scratch (device globals — no runtime allocation allowed)
__device__ float g_inner[(size_t)PADROWS * F_DIM];   // 40 MB (tf32-rounded values)
__device__ int   g_pair_token[PADROWS];
__device__ float g_pair_w[PADROWS];
__device__ int   g_topi[N_TOK * 2];
__device__ float g_topw[N_TOK * 2];
__device__ int   g_counts[E_NUM];
__device__ int   g_cursor[E_NUM];
__device__ int   g_tile_e[MAXTILES];

__device__ __forceinline__ uint32_t f2tf(float f) {
    uint32_t u;
    asm("cvt.rna.tf32.f32 %0, %1;" : "=r"(u) : "f"(f));
    return u;
}

// ---------------------------------------------------------------------------
// init: zero output, reset counts, poison pair tokens
// ---------------------------------------------------------------------------
__global__ void init_kernel(float* out, int out_size) {
    int idx = blockIdx.x * blockDim.x + threadIdx.x;
    if (idx < out_size) out[idx] = 0.f;
    if (idx < PADROWS)  g_pair_token[idx] = -1;
    if (idx < E_NUM)    g_counts[idx] = 0;
}

// ---------------------------------------------------------------------------
// router: one warp per token. logits = x @ Wg; top-2 (softmax denom cancels)
// ---------------------------------------------------------------------------
__global__ void router_kernel(const float* __restrict__ x,
                              const float* __restrict__ Wg) {
    int warp = threadIdx.x >> 5;
    int lane = threadIdx.x & 31;
    int n = blockIdx.x * 8 + warp;
    if (n >= N_TOK) return;

    float acc[E_NUM];
#pragma unroll
    for (int e = 0; e < E_NUM; e++) acc[e] = 0.f;

    const float* xr = x + (size_t)n * D_DIM;
    for (int d = lane; d < D_DIM; d += 32) {
        float xv = xr[d];
#pragma unroll
        for (int e = 0; e < E_NUM; e++) acc[e] += xv * Wg[d * E_NUM + e];
    }
#pragma unroll
    for (int e = 0; e < E_NUM; e++) {
#pragma unroll
        for (int off = 16; off > 0; off >>= 1)
            acc[e] += __shfl_xor_sync(0xffffffffu, acc[e], off);
    }
    if (lane == 0) {
        float m = acc[0];
#pragma unroll
        for (int e = 1; e < E_NUM; e++) m = fmaxf(m, acc[e]);
        float p[E_NUM];
#pragma unroll
        for (int e = 0; e < E_NUM; e++) p[e] = expf(acc[e] - m);
        // top-2 (strict > keeps earliest index on ties, matching jax top_k)
        int i1 = 0;
#pragma unroll
        for (int e = 1; e < E_NUM; e++) if (p[e] > p[i1]) i1 = e;
        int i2 = (i1 == 0) ? 1 : 0;
#pragma unroll
        for (int e = 0; e < E_NUM; e++)
            if (e != i1 && p[e] > p[i2]) i2 = e;
        float inv = 1.f / (p[i1] + p[i2]);  // softmax denominator cancels
        g_topi[n * 2 + 0] = i1;  g_topw[n * 2 + 0] = p[i1] * inv;
        g_topi[n * 2 + 1] = i2;  g_topw[n * 2 + 1] = p[i2] * inv;
        atomicAdd(&g_counts[i1], 1);
        atomicAdd(&g_counts[i2], 1);
    }
}

// ---------------------------------------------------------------------------
// setup: padded segment starts, tile->expert map, cursor init (1 thread)
// ---------------------------------------------------------------------------
__global__ void setup_kernel() {
    if (threadIdx.x != 0 || blockIdx.x != 0) return;
    int off = 0;
    int pad[E_NUM];
    for (int e = 0; e < E_NUM; e++) {
        g_cursor[e] = off;
        int p = ((g_counts[e] + BM - 1) / BM) * BM;
        pad[e] = p;
        off += p;
    }
    int t = 0;
    for (int e = 0; e < E_NUM; e++)
        for (int r = 0; r < pad[e]; r += BM) g_tile_e[t++] = e;
    for (; t < MAXTILES; t++) g_tile_e[t] = -1;
}

// ---------------------------------------------------------------------------
// scatter: pairs -> padded per-expert rows
// ---------------------------------------------------------------------------
__global__ void scatter_kernel() {
    int idx = blockIdx.x * blockDim.x + threadIdx.x;
    if (idx >= NPAIR) return;
    int e = g_topi[idx];
    int pos = atomicAdd(&g_cursor[e], 1);
    g_pair_token[pos] = idx >> 1;
    g_pair_w[pos] = g_topw[idx];
}

// ---------------------------------------------------------------------------
// mma.sync m16n8k8 tf32 (fp32 accum)
// ---------------------------------------------------------------------------
__device__ __forceinline__ void mma_tf32(float c[4], const uint32_t a[4],
                                         const uint32_t b[2]) {
    asm volatile(
        "mma.sync.aligned.m16n8k8.row.col.f32.tf32.tf32.f32 "
        "{%0,%1,%2,%3}, {%4,%5,%6,%7}, {%8,%9}, {%0,%1,%2,%3};\n"
        : "+f"(c[0]), "+f"(c[1]), "+f"(c[2]), "+f"(c[3])
        : "r"(a[0]), "r"(a[1]), "r"(a[2]), "r"(a[3]), "r"(b[0]), "r"(b[1]));
}

// Load A fragment (m16k8) from smem [row][col] layout with stride LDA.
__device__ __forceinline__ void loadA(uint32_t a[4], const uint32_t* As,
                                      int row0, int kb, int g4, int t4) {
    const uint32_t* p = As + (size_t)row0 * LDA + kb;
    a[0] = p[(size_t)g4 * LDA + t4];
    a[1] = p[(size_t)(g4 + 8) * LDA + t4];
    a[2] = p[(size_t)g4 * LDA + t4 + 4];
    a[3] = p[(size_t)(g4 + 8) * LDA + t4 + 4];
}

__device__ __forceinline__ void loadB(uint32_t b[2], const uint32_t* Bs,
                                      int n, int kb, int t4) {
    const uint32_t* p = Bs + (size_t)n * LDB + kb;
    b[0] = p[t4];
    b[1] = p[t4 + 4];
}

// ---------------------------------------------------------------------------
// GEMM1: inner = gelu(X@W_in + b_in) * (X@W_scale + b_scale)  (tf32 out)
// Grid: (F_DIM/BN, MAXTILES). 8 warps: 4 in M (32 rows), 2 in N (32 cols).
// ---------------------------------------------------------------------------
__global__ __launch_bounds__(256) void gemm1_kernel(
    const float* __restrict__ x,   const float* __restrict__ Win,
    const float* __restrict__ bin, const float* __restrict__ Wsc,
    const float* __restrict__ bsc) {
    int e = g_tile_e[blockIdx.y];
    if (e < 0) return;
    int row0 = blockIdx.y * BM;
    int n0   = blockIdx.x * BN;

    __shared__ __align__(16) uint32_t As[BM * LDA];
    __shared__ __align__(16) uint32_t B1s[BN * LDB];
    __shared__ __align__(16) uint32_t B2s[BN * LDB];

    int tid = threadIdx.x;
    int lane = tid & 31, warp = tid >> 5;
    int wm = warp & 3, wn = warp >> 2;
    int g4 = lane >> 2, t4 = lane & 3;

    float cH[2][4][4], cS[2][4][4];
#pragma unroll
    for (int mi = 0; mi < 2; mi++)
#pragma unroll
        for (int ni = 0; ni < 4; ni++)
#pragma unroll
            for (int j = 0; j < 4; j++) { cH[mi][ni][j] = 0.f; cS[mi][ni][j] = 0.f; }

    int tokA[4];
#pragma unroll
    for (int i = 0; i < 4; i++) tokA[i] = g_pair_token[row0 + ((tid + i * 256) >> 3)];

    for (int k0 = 0; k0 < D_DIM; k0 += BK) {
        // A: gather 128x32 fp32 -> tf32 smem (8 float4 per row)
#pragma unroll
        for (int i = 0; i < 4; i++) {
            int vid = tid + i * 256;
            int r = vid >> 3, kv = vid & 7;
            float4 v = make_float4(0.f, 0.f, 0.f, 0.f);
            if (tokA[i] >= 0)
                v = *(const float4*)(x + (size_t)tokA[i] * D_DIM + k0 + kv * 4);
            uint4 u = make_uint4(f2tf(v.x), f2tf(v.y), f2tf(v.z), f2tf(v.w));
            *(uint4*)(As + (size_t)r * LDA + kv * 4) = u;
        }
        // B: 32x64 slices of W_in / W_scale, transposed to [n][k], tf32
#pragma unroll
        for (int i = 0; i < 2; i++) {
            int vid = tid + i * 256;
            int k = vid >> 4, nv = vid & 15;
            size_t base = ((size_t)e * D_DIM + k0 + k) * F_DIM + n0 + nv * 4;
            float4 v1 = *(const float4*)(Win + base);
            float4 v2 = *(const float4*)(Wsc + base);
            int nb = nv * 4;
            B1s[(size_t)(nb + 0) * LDB + k] = f2tf(v1.x);
            B1s[(size_t)(nb + 1) * LDB + k] = f2tf(v1.y);
            B1s[(size_t)(nb + 2) * LDB + k] = f2tf(v1.z);
            B1s[(size_t)(nb + 3) * LDB + k] = f2tf(v1.w);
            B2s[(size_t)(nb + 0) * LDB + k] = f2tf(v2.x);
            B2s[(size_t)(nb + 1) * LDB + k] = f2tf(v2.y);
            B2s[(size_t)(nb + 2) * LDB + k] = f2tf(v2.z);
            B2s[(size_t)(nb + 3) * LDB + k] = f2tf(v2.w);
        }
        __syncthreads();
#pragma unroll
        for (int kb = 0; kb < BK; kb += 8) {
            uint32_t a[2][4];
#pragma unroll
            for (int mi = 0; mi < 2; mi++)
                loadA(a[mi], As, wm * 32 + mi * 16, kb, g4, t4);
#pragma unroll
            for (int ni = 0; ni < 4; ni++) {
                uint32_t b1[2], b2[2];
                loadB(b1, B1s, wn * 32 + ni * 8 + g4, kb, t4);
                loadB(b2, B2s, wn * 32 + ni * 8 + g4, kb, t4);
#pragma unroll
                for (int mi = 0; mi < 2; mi++) {
                    mma_tf32(cH[mi][ni], a[mi], b1);
                    mma_tf32(cS[mi][ni], a[mi], b2);
                }
            }
        }
        __syncthreads();
    }
    // epilogue: exact GELU gate, tf32-rounded fp32 store
#pragma unroll
    for (int mi = 0; mi < 2; mi++) {
#pragma unroll
        for (int ni = 0; ni < 4; ni++) {
            int col = n0 + wn * 32 + ni * 8 + t4 * 2;
            float bi0 = bin[e * F_DIM + col], bi1 = bin[e * F_DIM + col + 1];
            float bs0 = bsc[e * F_DIM + col], bs1 = bsc[e * F_DIM + col + 1];
#pragma unroll
            for (int h = 0; h < 2; h++) {
                int row = row0 + wm * 32 + mi * 16 + g4 + h * 8;
                float h0 = cH[mi][ni][h * 2 + 0] + bi0;
                float h1 = cH[mi][ni][h * 2 + 1] + bi1;
                float s0 = cS[mi][ni][h * 2 + 0] + bs0;
                float s1 = cS[mi][ni][h * 2 + 1] + bs1;
                float gl0 = 0.5f * h0 * (1.f + erff(h0 * 0.70710678118654752f));
                float gl1 = 0.5f * h1 * (1.f + erff(h1 * 0.70710678118654752f));
                float2 o;
                o.x = __uint_as_float(f2tf(gl0 * s0));
                o.y = __uint_as_float(f2tf(gl1 * s1));
                *(float2*)(g_inner + (size_t)row * F_DIM + col) = o;
            }
        }
    }
}

// ---------------------------------------------------------------------------
// GEMM2: y = inner @ W_out + b_out; out[token] += gate * y (atomic)
// Grid: (D_DIM/BN, MAXTILES)
// ---------------------------------------------------------------------------
__global__ __launch_bounds__(256) void gemm2_kernel(
    const float* __restrict__ Wout, const float* __restrict__ bout,
    float* __restrict__ out) {
    int e = g_tile_e[blockIdx.y];
    if (e < 0) return;
    int row0 = blockIdx.y * BM;
    int n0   = blockIdx.x * BN;

    __shared__ __align__(16) uint32_t As[BM * LDA];
    __shared__ __align__(16) uint32_t Bs[BN * LDB];

    int tid = threadIdx.x;
    int lane = tid & 31, warp = tid >> 5;
    int wm = warp & 3, wn = warp >> 2;
    int g4 = lane >> 2, t4 = lane & 3;

    float c[2][4][4];
#pragma unroll
    for (int mi = 0; mi < 2; mi++)
#pragma unroll
        for (int ni = 0; ni < 4; ni++)
#pragma unroll
            for (int j = 0; j < 4; j++) c[mi][ni][j] = 0.f;

    for (int k0 = 0; k0 < F_DIM; k0 += BK) {
        // A: inner is already tf32-rounded fp32, straight vector copies
#pragma unroll
        for (int i = 0; i < 4; i++) {
            int vid = tid + i * 256;
            int r = vid >> 3, q = vid & 7;
            uint4 v = *(const uint4*)(g_inner + (size_t)(row0 + r) * F_DIM + k0 + q * 4);
            *(uint4*)(As + (size_t)r * LDA + q * 4) = v;
        }
        // B: W_out slice [BK x BN] fp32 -> tf32, transposed
#pragma unroll
        for (int i = 0; i < 2; i++) {
            int vid = tid + i * 256;
            int k = vid >> 4, nv = vid & 15;
            float4 v = *(const float4*)(Wout + ((size_t)e * F_DIM + k0 + k) * D_DIM + n0 + nv * 4);
            int nb = nv * 4;
            Bs[(size_t)(nb + 0) * LDB + k] = f2tf(v.x);
            Bs[(size_t)(nb + 1) * LDB + k] = f2tf(v.y);
            Bs[(size_t)(nb + 2) * LDB + k] = f2tf(v.z);
            Bs[(size_t)(nb + 3) * LDB + k] = f2tf(v.w);
        }
        __syncthreads();
#pragma unroll
        for (int kb = 0; kb < BK; kb += 8) {
            uint32_t a[2][4];
#pragma unroll
            for (int mi = 0; mi < 2; mi++)
                loadA(a[mi], As, wm * 32 + mi * 16, kb, g4, t4);
#pragma unroll
            for (int ni = 0; ni < 4; ni++) {
                uint32_t b[2];
                loadB(b, Bs, wn * 32 + ni * 8 + g4, kb, t4);
#pragma unroll
                for (int mi = 0; mi < 2; mi++) mma_tf32(c[mi][ni], a[mi], b);
            }
        }
        __syncthreads();
    }
    // epilogue: gate-weighted atomic accumulate into out
#pragma unroll
    for (int mi = 0; mi < 2; mi++) {
#pragma unroll
        for (int ni = 0; ni < 4; ni++) {
            int col = n0 + wn * 32 + ni * 8 + t4 * 2;
            float b0 = bout[e * D_DIM + col], b1 = bout[e * D_DIM + col + 1];
#pragma unroll
            for (int h = 0; h < 2; h++) {
                int rowp = row0 + wm * 32 + mi * 16 + g4 + h * 8;
                int tok = g_pair_token[rowp];
                if (tok >= 0) {
                    float w = g_pair_w[rowp];
                    atomicAdd(&out[(size_t)tok * D_DIM + col],     w * (c[mi][ni][h * 2 + 0] + b0));
                    atomicAdd(&out[(size_t)tok * D_DIM + col + 1], w * (c[mi][ni][h * 2 + 1] + b1));
                }
            }
        }
    }
}

// ---------------------------------------------------------------------------
extern "C" void kernel_launch(void* const* d_in, const int* in_sizes, int n_in,
                              void* d_out, int out_size) {
    const float* states = (const float*)d_in[0];
    const float* Wg     = (const float*)d_in[1];
    const float* Win    = (const float*)d_in[2];
    const float* bin    = (const float*)d_in[3];
    const float* Wsc    = (const float*)d_in[4];
    const float* bsc    = (const float*)d_in[5];
    const float* Wout   = (const float*)d_in[6];
    const float* bout   = (const float*)d_in[7];
    float* out = (float*)d_out;

    init_kernel<<<(out_size + 255) / 256, 256>>>(out, out_size);
    router_kernel<<<N_TOK / 8, 256>>>(states, Wg);
    setup_kernel<<<1, 32>>>();
    scatter_kernel<<<(NPAIR + 255) / 256, 256>>>();
    gemm1_kernel<<<dim3(F_DIM / BN, MAXTILES), 256>>>(states, Win, bin, Wsc, bsc);
    gemm2_kernel<<<dim3(D_DIM / BN, MAXTILES), 256>>>(Wout, bout, out);
}

// round 3
// speedup vs baseline: 1.0088x; 1.0088x over previous
#include <cuda_runtime.h>
#include <cuda_bf16.h>
#include <math.h>
#include <stdint.h>

// Problem constants (fixed by the dataset)
#define D_DIM   1024
#define F_DIM   2048
#define E_NUM   8
#define N_TOK   2048
#define NPAIR   4096   // N_TOK * K (K=2)
#define PADROWS 5120   // NPAIR + E_NUM*BM worst-case padding
#define BM      128
#define BN      64
#define BK      32
#define MAXTILES (PADROWS / BM)   // 40
#define LDA     36     // BK + 4 pad (fp32 elems); 144B row stride, 16B aligned
#define LDB     36

// Scratch (device globals — no runtime allocation allowed)
__device__ float g_inner[(size_t)PADROWS * F_DIM];   // 40 MB (tf32-rounded values)
__device__ int   g_pair_token[PADROWS];
__device__ float g_pair_w[PADROWS];
__device__ int   g_topi[N_TOK * 2];
__device__ float g_topw[N_TOK * 2];
__device__ int   g_counts[E_NUM];
__device__ int   g_cursor[E_NUM];
__device__ int   g_tile_e[MAXTILES];

__device__ __forceinline__ uint32_t f2tf(float f) {
    uint32_t u;
    asm("cvt.rna.tf32.f32 %0, %1;" : "=r"(u) : "f"(f));
    return u;
}

// ---------------------------------------------------------------------------
// init: zero output, reset counts, poison pair tokens
// ---------------------------------------------------------------------------
__global__ void init_kernel(float* out, int out_size) {
    int idx = blockIdx.x * blockDim.x + threadIdx.x;
    if (idx < out_size) out[idx] = 0.f;
    if (idx < PADROWS)  g_pair_token[idx] = -1;
    if (idx < E_NUM)    g_counts[idx] = 0;
}

// ---------------------------------------------------------------------------
// router: one warp per token. logits = x @ Wg; top-2 (softmax denom cancels)
// ---------------------------------------------------------------------------
__global__ void router_kernel(const float* __restrict__ x,
                              const float* __restrict__ Wg) {
    int warp = threadIdx.x >> 5;
    int lane = threadIdx.x & 31;
    int n = blockIdx.x * 8 + warp;
    if (n >= N_TOK) return;

    float acc[E_NUM];
#pragma unroll
    for (int e = 0; e < E_NUM; e++) acc[e] = 0.f;

    const float* xr = x + (size_t)n * D_DIM;
    for (int d = lane; d < D_DIM; d += 32) {
        float xv = xr[d];
#pragma unroll
        for (int e = 0; e < E_NUM; e++) acc[e] += xv * Wg[d * E_NUM + e];
    }
#pragma unroll
    for (int e = 0; e < E_NUM; e++) {
#pragma unroll
        for (int off = 16; off > 0; off >>= 1)
            acc[e] += __shfl_xor_sync(0xffffffffu, acc[e], off);
    }
    if (lane == 0) {
        float m = acc[0];
#pragma unroll
        for (int e = 1; e < E_NUM; e++) m = fmaxf(m, acc[e]);
        float p[E_NUM];
#pragma unroll
        for (int e = 0; e < E_NUM; e++) p[e] = expf(acc[e] - m);
        // top-2 (strict > keeps earliest index on ties, matching jax top_k)
        int i1 = 0;
#pragma unroll
        for (int e = 1; e < E_NUM; e++) if (p[e] > p[i1]) i1 = e;
        int i2 = (i1 == 0) ? 1 : 0;
#pragma unroll
        for (int e = 0; e < E_NUM; e++)
            if (e != i1 && p[e] > p[i2]) i2 = e;
        float inv = 1.f / (p[i1] + p[i2]);  // softmax denominator cancels
        g_topi[n * 2 + 0] = i1;  g_topw[n * 2 + 0] = p[i1] * inv;
        g_topi[n * 2 + 1] = i2;  g_topw[n * 2 + 1] = p[i2] * inv;
        atomicAdd(&g_counts[i1], 1);
        atomicAdd(&g_counts[i2], 1);
    }
}

// ---------------------------------------------------------------------------
// setup: padded segment starts, tile->expert map, cursor init (1 thread)
// ---------------------------------------------------------------------------
__global__ void setup_kernel() {
    if (threadIdx.x != 0 || blockIdx.x != 0) return;
    int off = 0;
    int pad[E_NUM];
    for (int e = 0; e < E_NUM; e++) {
        g_cursor[e] = off;
        int p = ((g_counts[e] + BM - 1) / BM) * BM;
        pad[e] = p;
        off += p;
    }
    int t = 0;
    for (int e = 0; e < E_NUM; e++)
        for (int r = 0; r < pad[e]; r += BM) g_tile_e[t++] = e;
    for (; t < MAXTILES; t++) g_tile_e[t] = -1;
}

// ---------------------------------------------------------------------------
// scatter: pairs -> padded per-expert rows
// ---------------------------------------------------------------------------
__global__ void scatter_kernel() {
    int idx = blockIdx.x * blockDim.x + threadIdx.x;
    if (idx >= NPAIR) return;
    int e = g_topi[idx];
    int pos = atomicAdd(&g_cursor[e], 1);
    g_pair_token[pos] = idx >> 1;
    g_pair_w[pos] = g_topw[idx];
}

// ---------------------------------------------------------------------------
// mma.sync m16n8k8 tf32 (fp32 accum)
// ---------------------------------------------------------------------------
__device__ __forceinline__ void mma_tf32(float c[4], const uint32_t a[4],
                                         const uint32_t b[2]) {
    asm volatile(
        "mma.sync.aligned.m16n8k8.row.col.f32.tf32.tf32.f32 "
        "{%0,%1,%2,%3}, {%4,%5,%6,%7}, {%8,%9}, {%0,%1,%2,%3};\n"
        : "+f"(c[0]), "+f"(c[1]), "+f"(c[2]), "+f"(c[3])
        : "r"(a[0]), "r"(a[1]), "r"(a[2]), "r"(a[3]), "r"(b[0]), "r"(b[1]));
}

// Load A fragment (m16k8) from smem [row][col] layout with stride LDA.
__device__ __forceinline__ void loadA(uint32_t a[4], const uint32_t* As,
                                      int row0, int kb, int g4, int t4) {
    const uint32_t* p = As + (size_t)row0 * LDA + kb;
    a[0] = p[(size_t)g4 * LDA + t4];
    a[1] = p[(size_t)(g4 + 8) * LDA + t4];
    a[2] = p[(size_t)g4 * LDA + t4 + 4];
    a[3] = p[(size_t)(g4 + 8) * LDA + t4 + 4];
}

__device__ __forceinline__ void loadB(uint32_t b[2], const uint32_t* Bs,
                                      int n, int kb, int t4) {
    const uint32_t* p = Bs + (size_t)n * LDB + kb;
    b[0] = p[t4];
    b[1] = p[t4 + 4];
}

// ---------------------------------------------------------------------------
// GEMM1: inner = gelu(X@W_in + b_in) * (X@W_scale + b_scale)  (tf32 out)
// Grid: (F_DIM/BN, MAXTILES). 8 warps: 4 in M (32 rows), 2 in N (32 cols).
// ---------------------------------------------------------------------------
__global__ __launch_bounds__(256) void gemm1_kernel(
    const float* __restrict__ x,   const float* __restrict__ Win,
    const float* __restrict__ bin, const float* __restrict__ Wsc,
    const float* __restrict__ bsc) {
    int e = g_tile_e[blockIdx.y];
    if (e < 0) return;
    int row0 = blockIdx.y * BM;
    int n0   = blockIdx.x * BN;

    __shared__ __align__(16) uint32_t As[BM * LDA];
    __shared__ __align__(16) uint32_t B1s[BN * LDB];
    __shared__ __align__(16) uint32_t B2s[BN * LDB];

    int tid = threadIdx.x;
    int lane = tid & 31, warp = tid >> 5;
    int wm = warp & 3, wn = warp >> 2;
    int g4 = lane >> 2, t4 = lane & 3;

    float cH[2][4][4], cS[2][4][4];
#pragma unroll
    for (int mi = 0; mi < 2; mi++)
#pragma unroll
        for (int ni = 0; ni < 4; ni++)
#pragma unroll
            for (int j = 0; j < 4; j++) { cH[mi][ni][j] = 0.f; cS[mi][ni][j] = 0.f; }

    int tokA[4];
#pragma unroll
    for (int i = 0; i < 4; i++) tokA[i] = g_pair_token[row0 + ((tid + i * 256) >> 3)];

    for (int k0 = 0; k0 < D_DIM; k0 += BK) {
        // A: gather 128x32 fp32 -> tf32 smem (8 float4 per row)
#pragma unroll
        for (int i = 0; i < 4; i++) {
            int vid = tid + i * 256;
            int r = vid >> 3, kv = vid & 7;
            float4 v = make_float4(0.f, 0.f, 0.f, 0.f);
            if (tokA[i] >= 0)
                v = *(const float4*)(x + (size_t)tokA[i] * D_DIM + k0 + kv * 4);
            uint4 u = make_uint4(f2tf(v.x), f2tf(v.y), f2tf(v.z), f2tf(v.w));
            *(uint4*)(As + (size_t)r * LDA + kv * 4) = u;
        }
        // B: 32x64 slices of W_in / W_scale, transposed to [n][k], tf32
#pragma unroll
        for (int i = 0; i < 2; i++) {
            int vid = tid + i * 256;
            int k = vid >> 4, nv = vid & 15;
            size_t base = ((size_t)e * D_DIM + k0 + k) * F_DIM + n0 + nv * 4;
            float4 v1 = *(const float4*)(Win + base);
            float4 v2 = *(const float4*)(Wsc + base);
            int nb = nv * 4;
            B1s[(size_t)(nb + 0) * LDB + k] = f2tf(v1.x);
            B1s[(size_t)(nb + 1) * LDB + k] = f2tf(v1.y);
            B1s[(size_t)(nb + 2) * LDB + k] = f2tf(v1.z);
            B1s[(size_t)(nb + 3) * LDB + k] = f2tf(v1.w);
            B2s[(size_t)(nb + 0) * LDB + k] = f2tf(v2.x);
            B2s[(size_t)(nb + 1) * LDB + k] = f2tf(v2.y);
            B2s[(size_t)(nb + 2) * LDB + k] = f2tf(v2.z);
            B2s[(size_t)(nb + 3) * LDB + k] = f2tf(v2.w);
        }
        __syncthreads();
#pragma unroll
        for (int kb = 0; kb < BK; kb += 8) {
            uint32_t a[2][4];
#pragma unroll
            for (int mi = 0; mi < 2; mi++)
                loadA(a[mi], As, wm * 32 + mi * 16, kb, g4, t4);
#pragma unroll
            for (int ni = 0; ni < 4; ni++) {
                uint32_t b1[2], b2[2];
                loadB(b1, B1s, wn * 32 + ni * 8 + g4, kb, t4);
                loadB(b2, B2s, wn * 32 + ni * 8 + g4, kb, t4);
#pragma unroll
                for (int mi = 0; mi < 2; mi++) {
                    mma_tf32(cH[mi][ni], a[mi], b1);
                    mma_tf32(cS[mi][ni], a[mi], b2);
                }
            }
        }
        __syncthreads();
    }
    // epilogue: exact GELU gate, tf32-rounded fp32 store
#pragma unroll
    for (int mi = 0; mi < 2; mi++) {
#pragma unroll
        for (int ni = 0; ni < 4; ni++) {
            int col = n0 + wn * 32 + ni * 8 + t4 * 2;
            float bi0 = bin[e * F_DIM + col], bi1 = bin[e * F_DIM + col + 1];
            float bs0 = bsc[e * F_DIM + col], bs1 = bsc[e * F_DIM + col + 1];
#pragma unroll
            for (int h = 0; h < 2; h++) {
                int row = row0 + wm * 32 + mi * 16 + g4 + h * 8;
                float h0 = cH[mi][ni][h * 2 + 0] + bi0;
                float h1 = cH[mi][ni][h * 2 + 1] + bi1;
                float s0 = cS[mi][ni][h * 2 + 0] + bs0;
                float s1 = cS[mi][ni][h * 2 + 1] + bs1;
                float gl0 = 0.5f * h0 * (1.f + erff(h0 * 0.70710678118654752f));
                float gl1 = 0.5f * h1 * (1.f + erff(h1 * 0.70710678118654752f));
                float2 o;
                o.x = __uint_as_float(f2tf(gl0 * s0));
                o.y = __uint_as_float(f2tf(gl1 * s1));
                *(float2*)(g_inner + (size_t)row * F_DIM + col) = o;
            }
        }
    }
}

// ---------------------------------------------------------------------------
// GEMM2: y = inner @ W_out + b_out; out[token] += gate * y (atomic)
// Grid: (D_DIM/BN, MAXTILES)
// ---------------------------------------------------------------------------
__global__ __launch_bounds__(256) void gemm2_kernel(
    const float* __restrict__ Wout, const float* __restrict__ bout,
    float* __restrict__ out) {
    int e = g_tile_e[blockIdx.y];
    if (e < 0) return;
    int row0 = blockIdx.y * BM;
    int n0   = blockIdx.x * BN;

    __shared__ __align__(16) uint32_t As[BM * LDA];
    __shared__ __align__(16) uint32_t Bs[BN * LDB];

    int tid = threadIdx.x;
    int lane = tid & 31, warp = tid >> 5;
    int wm = warp & 3, wn = warp >> 2;
    int g4 = lane >> 2, t4 = lane & 3;

    float c[2][4][4];
#pragma unroll
    for (int mi = 0; mi < 2; mi++)
#pragma unroll
        for (int ni = 0; ni < 4; ni++)
#pragma unroll
            for (int j = 0; j < 4; j++) c[mi][ni][j] = 0.f;

    for (int k0 = 0; k0 < F_DIM; k0 += BK) {
        // A: inner is already tf32-rounded fp32, straight vector copies
#pragma unroll
        for (int i = 0; i < 4; i++) {
            int vid = tid + i * 256;
            int r = vid >> 3, q = vid & 7;
            uint4 v = *(const uint4*)(g_inner + (size_t)(row0 + r) * F_DIM + k0 + q * 4);
            *(uint4*)(As + (size_t)r * LDA + q * 4) = v;
        }
        // B: W_out slice [BK x BN] fp32 -> tf32, transposed
#pragma unroll
        for (int i = 0; i < 2; i++) {
            int vid = tid + i * 256;
            int k = vid >> 4, nv = vid & 15;
            float4 v = *(const float4*)(Wout + ((size_t)e * F_DIM + k0 + k) * D_DIM + n0 + nv * 4);
            int nb = nv * 4;
            Bs[(size_t)(nb + 0) * LDB + k] = f2tf(v.x);
            Bs[(size_t)(nb + 1) * LDB + k] = f2tf(v.y);
            Bs[(size_t)(nb + 2) * LDB + k] = f2tf(v.z);
            Bs[(size_t)(nb + 3) * LDB + k] = f2tf(v.w);
        }
        __syncthreads();
#pragma unroll
        for (int kb = 0; kb < BK; kb += 8) {
            uint32_t a[2][4];
#pragma unroll
            for (int mi = 0; mi < 2; mi++)
                loadA(a[mi], As, wm * 32 + mi * 16, kb, g4, t4);
#pragma unroll
            for (int ni = 0; ni < 4; ni++) {
                uint32_t b[2];
                loadB(b, Bs, wn * 32 + ni * 8 + g4, kb, t4);
#pragma unroll
                for (int mi = 0; mi < 2; mi++) mma_tf32(c[mi][ni], a[mi], b);
            }
        }
        __syncthreads();
    }
    // epilogue: gate-weighted atomic accumulate into out
#pragma unroll
    for (int mi = 0; mi < 2; mi++) {
#pragma unroll
        for (int ni = 0; ni < 4; ni++) {
            int col = n0 + wn * 32 + ni * 8 + t4 * 2;
            float b0 = bout[e * D_DIM + col], b1 = bout[e * D_DIM + col + 1];
#pragma unroll
            for (int h = 0; h < 2; h++) {
                int rowp = row0 + wm * 32 + mi * 16 + g4 + h * 8;
                int tok = g_pair_token[rowp];
                if (tok >= 0) {
                    float w = g_pair_w[rowp];
                    atomicAdd(&out[(size_t)tok * D_DIM + col],     w * (c[mi][ni][h * 2 + 0] + b0));
                    atomicAdd(&out[(size_t)tok * D_DIM + col + 1], w * (c[mi][ni][h * 2 + 1] + b1));
                }
            }
        }
    }
}

// ---------------------------------------------------------------------------
extern "C" void kernel_launch(void* const* d_in, const int* in_sizes, int n_in,
                              void* d_out, int out_size) {
    const float* states = (const float*)d_in[0];
    const float* Wg     = (const float*)d_in[1];
    const float* Win    = (const float*)d_in[2];
    const float* bin    = (const float*)d_in[3];
    const float* Wsc    = (const float*)d_in[4];
    const float* bsc    = (const float*)d_in[5];
    const float* Wout   = (const float*)d_in[6];
    const float* bout   = (const float*)d_in[7];
    float* out = (float*)d_out;

    init_kernel<<<(out_size + 255) / 256, 256>>>(out, out_size);
    router_kernel<<<N_TOK / 8, 256>>>(states, Wg);
    setup_kernel<<<1, 32>>>();
    scatter_kernel<<<(NPAIR + 255) / 256, 256>>>();
    gemm1_kernel<<<dim3(F_DIM / BN, MAXTILES), 256>>>(states, Win, bin, Wsc, bsc);
    gemm2_kernel<<<dim3(D_DIM / BN, MAXTILES), 256>>>(Wout, bout, out);
}